// round 16
// baseline (speedup 1.0000x reference)
#include <cuda_runtime.h>
#include <cuda_bf16.h>
#include <math_constants.h>
#include <cstdint>

#define NPTS 8192
#define CCH  256
#define KNB  16

typedef unsigned long long ull;

// ---------------- pack helpers ----------------
// f16x2: bits[15:0] = lo arg, bits[31:16] = hi arg
__device__ __forceinline__ uint32_t f16pack(float lo, float hi) {
    uint32_t r;
    asm("cvt.rn.f16x2.f32 %0, %1, %2;" : "=r"(r) : "f"(hi), "f"(lo));
    return r;
}
// 4x e4m3 bytes: f0 -> byte0 (lowest), f3 -> byte3
__device__ __forceinline__ uint32_t e4m3x4(float f0, float f1, float f2, float f3) {
    uint32_t r;
    asm("{\n\t.reg .b16 lo, hi;\n\t"
        "cvt.rn.satfinite.e4m3x2.f32 lo, %2, %1;\n\t"
        "cvt.rn.satfinite.e4m3x2.f32 hi, %4, %3;\n\t"
        "mov.b32 %0, {lo, hi};\n\t}"
        : "=r"(r) : "f"(f0), "f"(f1), "f"(f2), "f"(f3));
    return r;
}

// mma.sync f16 m16n8k16 (baseline sm_80 PTX)
__device__ __forceinline__ void mma_f16(float* d,
                                        uint32_t a0, uint32_t a1, uint32_t a2, uint32_t a3,
                                        uint32_t b0, uint32_t b1) {
    asm volatile(
        "mma.sync.aligned.m16n8k16.row.col.f32.f16.f16.f32 "
        "{%0,%1,%2,%3}, {%4,%5,%6,%7}, {%8,%9}, {%0,%1,%2,%3};"
        : "+f"(d[0]), "+f"(d[1]), "+f"(d[2]), "+f"(d[3])
        : "r"(a0), "r"(a1), "r"(a2), "r"(a3), "r"(b0), "r"(b1));
}
// mma.sync fp8 e4m3 m16n8k32 (baseline sm_89 PTX)
__device__ __forceinline__ void mma_e4m3(float* d,
                                         uint32_t a0, uint32_t a1, uint32_t a2, uint32_t a3,
                                         uint32_t b0, uint32_t b1) {
    asm volatile(
        "mma.sync.aligned.m16n8k32.row.col.f32.e4m3.e4m3.f32 "
        "{%0,%1,%2,%3}, {%4,%5,%6,%7}, {%8,%9}, {%0,%1,%2,%3};"
        : "+f"(d[0]), "+f"(d[1]), "+f"(d[2]), "+f"(d[3])
        : "r"(a0), "r"(a1), "r"(a2), "r"(a3), "r"(b0), "r"(b1));
}

// ---------------- scratch (device globals; no allocation APIs) ----------------
__device__ int    g_idx[NPTS * KNB];
__device__ float  g_theta[NPTS * CCH];
__device__ float  g_phi[NPTS * CCH];
__device__ float  g_gv[NPTS * CCH];
__device__ float  g_y[NPTS * CCH];
__device__ uint32_t g_w2f[16384];        // attn w2 -> e4m3 B fragments
__device__ uint32_t g_wf[4 * 32768];     // theta/phi/g/W -> fp16 B fragments
// grid-KNN scratch
__device__ float4 g_spts[NPTS];
__device__ int    g_sid[NPTS];
__device__ int    g_cellstart[513];

#define GRID_DIM 8
#define CELL_H   12.5f
#define INV_H    0.08f

__device__ __forceinline__ int cell_coord(float v) {
    int c = (int)(v * INV_H);
    return min(GRID_DIM - 1, max(0, c));
}

// ---------------- fused grid build: hist + scan + scatter in ONE block ----------------
__global__ __launch_bounds__(1024) void build_grid_kernel(const float* __restrict__ coords) {
    __shared__ int scnt[512];
    __shared__ int sbase[512];
    int t = threadIdx.x;
    if (t < 512) scnt[t] = 0;
    __syncthreads();

    float px[8], py[8], pz[8];
    int pc[8];
#pragma unroll
    for (int u = 0; u < 8; ++u) {
        int i = t + u * 1024;
        float x = coords[3 * i + 0];
        float y = coords[3 * i + 1];
        float z = coords[3 * i + 2];
        px[u] = x; py[u] = y; pz[u] = z;
        int cell = (cell_coord(z) * GRID_DIM + cell_coord(y)) * GRID_DIM + cell_coord(x);
        pc[u] = cell;
        atomicAdd(&scnt[cell], 1);
    }
    __syncthreads();

    if (t < 512) sbase[t] = scnt[t];
    __syncthreads();
    for (int off = 1; off < 512; off <<= 1) {
        int a = 0;
        if (t < 512 && t >= off) a = sbase[t - off];
        __syncthreads();
        if (t < 512) sbase[t] += a;
        __syncthreads();
    }
    if (t < 512) {
        g_cellstart[t + 1] = sbase[t];
        if (t == 0) g_cellstart[0] = 0;
    }
    __syncthreads();
    if (t < 512) { sbase[t] -= scnt[t]; scnt[t] = 0; }   // exclusive base + cursor reset
    __syncthreads();

#pragma unroll
    for (int u = 0; u < 8; ++u) {
        int i = t + u * 1024;
        int cell = pc[u];
        int pos = sbase[cell] + atomicAdd(&scnt[cell], 1);
        float x = px[u], y = py[u], z = pz[u];
        g_spts[pos] = make_float4(x, y, z, x * x + y * y + z * z);
        g_sid[pos] = i;
    }
}

// ---------------- grid KNN: warp/query, bitonic seed + lean exact inserts ----------------
__global__ __launch_bounds__(256) void knn_grid_kernel(const float* __restrict__ coords) {
    int warp = threadIdx.x >> 5;
    int lane = threadIdx.x & 31;
    int q = blockIdx.x * 8 + warp;

    float qx = coords[3 * q + 0];
    float qy = coords[3 * q + 1];
    float qz = coords[3 * q + 2];
    float qw = qx * qx + qy * qy + qz * qz;
    int cx = cell_coord(qx), cy = cell_coord(qy), cz = cell_coord(qz);

    ull slot = ~0ull;
    ull thr  = ~0ull;
    float thrf = CUDART_INF_F;
    bool seeded = false;

    auto scan_range = [&](int c0, int c1) {
        int st = g_cellstart[c0];
        int en = g_cellstart[c1 + 1];
        for (int jj = st; jj < en; jj += 32) {
            int id = jj + lane;
            ull key = ~0ull;
            if (id < en) {
                float4 p = g_spts[id];
                float dot = qx * p.x + qy * p.y + qz * p.z;
                float d2 = (qw + p.w) - 2.0f * dot;   // reference formula
                if (d2 <= thrf) {
                    unsigned u = __float_as_uint(d2);
                    u = ((int)u < 0) ? ~u : (u | 0x80000000u);
                    key = ((ull)u << 32) | (unsigned)g_sid[id];
                }
            }
            if (!seeded) {
#pragma unroll
                for (int k = 2; k <= 32; k <<= 1) {
#pragma unroll
                    for (int j = k >> 1; j > 0; j >>= 1) {
                        ull other = __shfl_xor_sync(0xffffffffu, key, j);
                        bool keepSmall = (((lane & k) == 0) == ((lane & j) == 0));
                        bool less = key < other;
                        key = (keepSmall == less) ? key : other;
                    }
                }
                slot = key;
                thr  = __shfl_sync(0xffffffffu, slot, 15);
                seeded = true;
            } else {
                unsigned mask = __ballot_sync(0xffffffffu, key < thr);
                if (mask) {
                    while (mask) {
                        int src = __ffs(mask) - 1;
                        mask &= mask - 1;
                        ull cand = __shfl_sync(0xffffffffu, key, src);
                        unsigned lt = __ballot_sync(0xffffffffu, (lane < 16) && (slot < cand));
                        int pos = __popc(lt);
                        ull prev = __shfl_up_sync(0xffffffffu, slot, 1);
                        if (lane >= pos && lane < 16) slot = (lane == pos) ? cand : prev;
                    }
                    thr = __shfl_sync(0xffffffffu, slot, 15);
                }
            }
        }
        unsigned hb = (unsigned)(thr >> 32);
        thrf = (hb == 0xffffffffu) ? CUDART_INF_F
             : ((hb & 0x80000000u) ? __uint_as_float(hb & 0x7fffffffu)
                                   : __uint_as_float(~hb));
    };

    int px0 = 1, px1 = 0, py0 = 1, py1 = 0, pz0 = 1, pz1 = 0;

    for (int s = 1; s <= GRID_DIM; ++s) {
        int x0 = max(cx - s, 0), x1 = min(cx + s, GRID_DIM - 1);
        int y0 = max(cy - s, 0), y1 = min(cy + s, GRID_DIM - 1);
        int z0 = max(cz - s, 0), z1 = min(cz + s, GRID_DIM - 1);

        for (int zz = z0; zz <= z1; ++zz)
        for (int yy = y0; yy <= y1; ++yy) {
            int rbase = (zz * GRID_DIM + yy) * GRID_DIM;
            bool inPrevZY = (zz >= pz0 && zz <= pz1 && yy >= py0 && yy <= py1);
            if (!inPrevZY) {
                scan_range(rbase + x0, rbase + x1);
            } else {
                if (x0 < px0) scan_range(rbase + x0, rbase + px0 - 1);
                if (px1 < x1) scan_range(rbase + px1 + 1, rbase + x1);
            }
        }

        bool covered = (x0 == 0 && x1 == GRID_DIM - 1 &&
                        y0 == 0 && y1 == GRID_DIM - 1 &&
                        z0 == 0 && z1 == GRID_DIM - 1);
        float fxl = (x0 > 0) ? qx - x0 * CELL_H : CUDART_INF_F;
        float fxh = (x1 < GRID_DIM - 1) ? (x1 + 1) * CELL_H - qx : CUDART_INF_F;
        float fyl = (y0 > 0) ? qy - y0 * CELL_H : CUDART_INF_F;
        float fyh = (y1 < GRID_DIM - 1) ? (y1 + 1) * CELL_H - qy : CUDART_INF_F;
        float fzl = (z0 > 0) ? qz - z0 * CELL_H : CUDART_INF_F;
        float fzh = (z1 < GRID_DIM - 1) ? (z1 + 1) * CELL_H - qz : CUDART_INF_F;
        float md = fminf(fminf(fminf(fxl, fxh), fminf(fyl, fyh)), fminf(fzl, fzh));
        if (covered || md * md > thrf + 0.5f) break;

        px0 = x0; px1 = x1; py0 = y0; py1 = y1; pz0 = z0; pz1 = z1;
    }

    if (lane < 16) g_idx[q * KNB + lane] = (int)(unsigned)(slot & 0xffffffffu);
}

// ---------------- prep: all weight fragments in one launch ----------------
// blocks 0..63:   attn w2 -> e4m3 B fragments (m16n8k32 layout)
// blocks 64..575: theta/phi/g/W -> fp16 B fragments (m16n8k16 layout)
__global__ void prep_frags_kernel(const float* __restrict__ w2attn,
                                  const float* __restrict__ w0, const float* __restrict__ w1,
                                  const float* __restrict__ w2, const float* __restrict__ w3) {
    if (blockIdx.x < 64) {
        int tid = blockIdx.x * 256 + threadIdx.x;       // 0..16383
        int reg = tid & 1;
        int ln  = (tid >> 1) & 31;
        int nt  = (tid >> 6) & 7;
        int kt  = (tid >> 9) & 7;
        int cc  = (tid >> 12) & 3;
        int n  = cc * 64 + nt * 8 + (ln >> 2);
        int k0 = kt * 32 + 4 * (ln & 3) + reg * 16;
        g_w2f[tid] = e4m3x4(w2attn[k0 * CCH + n],       w2attn[(k0 + 1) * CCH + n],
                            w2attn[(k0 + 2) * CCH + n], w2attn[(k0 + 3) * CCH + n]);
    } else {
        int tid = (blockIdx.x - 64) * 256 + threadIdx.x;  // 0..131071
        int m = tid >> 15;
        int r = tid & 32767;
        int reg = r & 1;
        int ln  = (r >> 1) & 31;
        int nt  = (r >> 6) & 31;
        int kt  = (r >> 11) & 15;
        int n = nt * 8 + (ln >> 2);
        int k = kt * 16 + 2 * (ln & 3) + reg * 8;
        const float* W = (m == 0) ? w0 : (m == 1) ? w1 : (m == 2) ? w2 : w3;
        g_wf[tid] = f16pack(W[k * CCH + n], W[(k + 1) * CCH + n]);
    }
}

// ---------------- tensor-core linear: fp16 single-pass ----------------
#define LIN_SMEM (64 * 132 * 4)

__global__ void __launch_bounds__(256, 2) linear_tc_kernel(
    const float* __restrict__ A, int m0,
    const float* __restrict__ b0_, const float* __restrict__ b1_, const float* __restrict__ b2_,
    float* __restrict__ o0, float* __restrict__ o1, float* __restrict__ o2,
    const float* __restrict__ resid)
{
    extern __shared__ uint32_t dsm[];
    uint32_t* sA = dsm;

    int mat = m0 + blockIdx.y;
    const float* bias = (blockIdx.y == 0) ? b0_ : (blockIdx.y == 1) ? b1_ : b2_;
    float*       out  = (blockIdx.y == 0) ? o0 : (blockIdx.y == 1) ? o1 : o2;

    int t = threadIdx.x;
    int lane = t & 31;
    int w = t >> 5;
    int wm = w & 3;
    int wn = w >> 2;
    int g = lane >> 2;
    int c4 = lane & 3;
    int row0 = blockIdx.x * 64;

    for (int idx = t; idx < 4096; idx += 256) {
        int row = idx >> 6;
        int qq = idx & 63;
        float4 v = *(const float4*)&A[(row0 + row) * CCH + qq * 4];
        *(uint2*)&sA[row * 132 + qq * 2] = make_uint2(f16pack(v.x, v.y), f16pack(v.z, v.w));
    }
    __syncthreads();

    float acc[16][4];
#pragma unroll
    for (int nt = 0; nt < 16; ++nt)
#pragma unroll
        for (int r = 0; r < 4; ++r) acc[nt][r] = 0.0f;

    int rA = wm * 16 + g;
    const uint32_t* bfrag = g_wf + mat * 32768;

#pragma unroll 2
    for (int kt = 0; kt < 16; ++kt) {
        uint32_t a0 = sA[rA * 132 + kt * 8 + c4];
        uint32_t a1 = sA[(rA + 8) * 132 + kt * 8 + c4];
        uint32_t a2 = sA[rA * 132 + kt * 8 + c4 + 4];
        uint32_t a3 = sA[(rA + 8) * 132 + kt * 8 + c4 + 4];
#pragma unroll
        for (int nt = 0; nt < 16; ++nt) {
            int ntg = wn * 16 + nt;
            uint2 bh = *(const uint2*)&bfrag[kt * 2048 + ntg * 64 + lane * 2];
            mma_f16(acc[nt], a0, a1, a2, a3, bh.x, bh.y);
        }
    }

#pragma unroll
    for (int nt = 0; nt < 16; ++nt) {
        int ntg = wn * 16 + nt;
        int n0 = ntg * 8 + 2 * c4;
        float2 bv = *(const float2*)&bias[n0];
        int r0 = row0 + rA;
        int r1 = r0 + 8;
        float2 v0 = make_float2(acc[nt][0] + bv.x, acc[nt][1] + bv.y);
        float2 v1 = make_float2(acc[nt][2] + bv.x, acc[nt][3] + bv.y);
        if (resid != nullptr) {
            float2 f0 = *(const float2*)&resid[r0 * CCH + n0];
            float2 f1 = *(const float2*)&resid[r1 * CCH + n0];
            v0.x += f0.x; v0.y += f0.y;
            v1.x += f1.x; v1.y += f1.y;
        }
        *(float2*)&out[r0 * CCH + n0] = v0;
        *(float2*)&out[r1 * CCH + n0] = v1;
    }
}

// ---------------- h-quad: 4 hidden values -> packed e4m3x4 fragment reg ----------------
__device__ __forceinline__ uint32_t hquad8(const float4* w1p4, int j0,
                                           float dx, float dy, float dz) {
    int p = j0 >> 1;      // j0 is even
    float4 a0 = w1p4[p * 2],     b0 = w1p4[p * 2 + 1];
    float4 a1 = w1p4[p * 2 + 2], b1 = w1p4[p * 2 + 3];
    float h0 = fmaxf(fmaf(dz, b0.x, fmaf(dy, a0.z, fmaf(dx, a0.x, b0.z))), 0.0f);
    float h1 = fmaxf(fmaf(dz, b0.y, fmaf(dy, a0.w, fmaf(dx, a0.y, b0.w))), 0.0f);
    float h2 = fmaxf(fmaf(dz, b1.x, fmaf(dy, a1.z, fmaf(dx, a1.x, b1.z))), 0.0f);
    float h3 = fmaxf(fmaf(dz, b1.y, fmaf(dy, a1.w, fmaf(dx, a1.y, b1.w))), 0.0f);
    return e4m3x4(h0, h1, h2, h3);
}

// ---------------- attention: fp8 mma pe-GEMM + warp-local softmax ----------------
// A-fragments (all K=256) precomputed once into 32 regs; cc loop = pure MMA + epilogue.
#define ATTN_SMEM_U32 5632
#define ATTN_SMEM_B   (ATTN_SMEM_U32 * 4)

__global__ void __launch_bounds__(256) attn_tc_kernel(
    const float* __restrict__ coords,
    const float* __restrict__ pe1_w1, const float* __restrict__ pe1_b1,
    const float* __restrict__ pe1_b2)
{
    extern __shared__ uint32_t dsm[];
    uint32_t* BH  = dsm;                    // 4096 u32 (16KB) per-chunk B frags
    float*    W1P = (float*)(dsm + 4096);   // 1024
    float*    DL  = (float*)(dsm + 5120);   // 384
    int*      ID  = (int*)(dsm + 5504);     // 128

    int t = threadIdx.x;
    int lane = t & 31;
    int w = t >> 5;
    int g = lane >> 2;
    int c4 = lane & 3;

    {
        int f = 4 * t;
#pragma unroll
        for (int u = 0; u < 4; ++u) {
            int ff = f + u, p = ff >> 3, comp = ff & 7;
            float v;
            if (comp < 6) v = pe1_w1[(comp >> 1) * CCH + 2 * p + (comp & 1)];
            else          v = pe1_b1[2 * p + (comp & 1)];
            W1P[ff] = v;
        }
    }
    if (t < 128) ID[t] = g_idx[blockIdx.x * 128 + t];
    __syncthreads();
    if (t < 128) {
        int nid = ID[t];
        int ip = blockIdx.x * 8 + (t >> 4);
#pragma unroll
        for (int d = 0; d < 3; ++d)
            DL[t * 3 + d] = coords[nid * 3 + d] - coords[ip * 3 + d];
    }
    __syncthreads();

    int rA = w * 16 + g, rB = rA + 8;
    float dxa = DL[rA * 3], dya = DL[rA * 3 + 1], dza = DL[rA * 3 + 2];
    float dxb = DL[rB * 3], dyb = DL[rB * 3 + 1], dzb = DL[rB * 3 + 2];
    int nid0 = ID[rA], nid1 = ID[rB];
    int ipt = blockIdx.x * 8 + w;

    const float4* w1p4 = (const float4*)W1P;

    // precompute ALL fp8 A-fragments (K=256 -> 8 kt x 4 regs)
    uint32_t afrag[32];
#pragma unroll
    for (int kt = 0; kt < 8; ++kt) {
        int j0 = kt * 32 + 4 * c4;
        afrag[kt * 4 + 0] = hquad8(w1p4, j0,      dxa, dya, dza);
        afrag[kt * 4 + 1] = hquad8(w1p4, j0,      dxb, dyb, dzb);
        afrag[kt * 4 + 2] = hquad8(w1p4, j0 + 16, dxa, dya, dza);
        afrag[kt * 4 + 3] = hquad8(w1p4, j0 + 16, dxb, dyb, dzb);
    }

    for (int cc = 0; cc < 4; ++cc) {
        __syncthreads();
        {   // stage this n-chunk's e4m3 B fragments (16KB)
            const uint4* sh = (const uint4*)(g_w2f + cc * 4096);
            uint4* dh = (uint4*)BH;
            for (int u = t; u < 1024; u += 256) dh[u] = sh[u];
        }
        __syncthreads();

        float acc[8][4];
#pragma unroll
        for (int nt = 0; nt < 8; ++nt)
#pragma unroll
            for (int r = 0; r < 4; ++r) acc[nt][r] = 0.0f;

#pragma unroll
        for (int kt = 0; kt < 8; ++kt) {
            const uint32_t* ap = afrag + kt * 4;
            int bbase = kt * 512 + lane * 2;
#pragma unroll
            for (int nt = 0; nt < 8; ++nt) {
                uint2 bh = *(const uint2*)&BH[bbase + nt * 64];
                mma_e4m3(acc[nt], ap[0], ap[1], ap[2], ap[3], bh.x, bh.y);
            }
        }

#pragma unroll
        for (int nt = 0; nt < 8; ++nt) {
            int n0 = cc * 64 + nt * 8 + 2 * c4;
            float2 b2v = *(const float2*)&pe1_b2[n0];
            float2 th  = *(const float2*)&g_theta[ipt * CCH + n0];
            float2 ph0 = *(const float2*)&g_phi[nid0 * CCH + n0];
            float2 ph1 = *(const float2*)&g_phi[nid1 * CCH + n0];

            float pe00 = acc[nt][0] + b2v.x, pe01 = acc[nt][1] + b2v.y;
            float pe10 = acc[nt][2] + b2v.x, pe11 = acc[nt][3] + b2v.y;

            float v00 = (pe00 * (th.x - ph0.x) + pe00) * 0.0625f;
            float v01 = (pe01 * (th.y - ph0.y) + pe01) * 0.0625f;
            float v10 = (pe10 * (th.x - ph1.x) + pe10) * 0.0625f;
            float v11 = (pe11 * (th.y - ph1.y) + pe11) * 0.0625f;

            float m0 = fmaxf(v00, v10), m1 = fmaxf(v01, v11);
#pragma unroll
            for (int off = 4; off <= 16; off <<= 1) {
                m0 = fmaxf(m0, __shfl_xor_sync(0xffffffffu, m0, off));
                m1 = fmaxf(m1, __shfl_xor_sync(0xffffffffu, m1, off));
            }
            float e00 = expf(v00 - m0), e10 = expf(v10 - m0);
            float e01 = expf(v01 - m1), e11 = expf(v11 - m1);
            float s0 = e00 + e10, s1 = e01 + e11;
#pragma unroll
            for (int off = 4; off <= 16; off <<= 1) {
                s0 += __shfl_xor_sync(0xffffffffu, s0, off);
                s1 += __shfl_xor_sync(0xffffffffu, s1, off);
            }
            float2 gv0 = *(const float2*)&g_gv[nid0 * CCH + n0];
            float2 gv1 = *(const float2*)&g_gv[nid1 * CCH + n0];
            float y0 = e00 * gv0.x + e10 * gv1.x;
            float y1 = e01 * gv0.y + e11 * gv1.y;
#pragma unroll
            for (int off = 4; off <= 16; off <<= 1) {
                y0 += __shfl_xor_sync(0xffffffffu, y0, off);
                y1 += __shfl_xor_sync(0xffffffffu, y1, off);
            }
            if (g == 0)
                *(float2*)&g_y[ipt * CCH + n0] = make_float2(y0 / s0, y1 / s1);
        }
    }
}

// ---------------- launch: fork KNN chain and GEMM-prep chain onto parallel streams ----------------
extern "C" void kernel_launch(void* const* d_in, const int* in_sizes, int n_in,
                              void* d_out, int out_size) {
    const float* coords  = (const float*)d_in[0];
    const float* feats   = (const float*)d_in[1];
    const float* theta_w = (const float*)d_in[2];
    const float* theta_b = (const float*)d_in[3];
    const float* phi_w   = (const float*)d_in[4];
    const float* phi_b   = (const float*)d_in[5];
    const float* g_w     = (const float*)d_in[6];
    const float* g_b     = (const float*)d_in[7];
    const float* pe1_w1  = (const float*)d_in[8];
    const float* pe1_b1  = (const float*)d_in[9];
    const float* pe1_w2  = (const float*)d_in[10];
    const float* pe1_b2  = (const float*)d_in[11];
    const float* W_w     = (const float*)d_in[12];
    const float* W_b     = (const float*)d_in[13];
    float* out = (float*)d_out;

    float *p_theta, *p_phi, *p_g, *p_y;
    cudaGetSymbolAddress((void**)&p_theta, g_theta);
    cudaGetSymbolAddress((void**)&p_phi,   g_phi);
    cudaGetSymbolAddress((void**)&p_g,     g_gv);
    cudaGetSymbolAddress((void**)&p_y,     g_y);

    cudaFuncSetAttribute(attn_tc_kernel,
                         cudaFuncAttributeMaxDynamicSharedMemorySize, ATTN_SMEM_B);
    cudaFuncSetAttribute(linear_tc_kernel,
                         cudaFuncAttributeMaxDynamicSharedMemorySize, LIN_SMEM);

    cudaStream_t s2;
    cudaStreamCreateWithFlags(&s2, cudaStreamNonBlocking);
    cudaEvent_t eFork, eJoin;
    cudaEventCreateWithFlags(&eFork, cudaEventDisableTiming);
    cudaEventCreateWithFlags(&eJoin, cudaEventDisableTiming);

    cudaEventRecord(eFork, 0);
    cudaStreamWaitEvent(s2, eFork, 0);

    // branch B (s2): weight fragments + theta/phi/g linears
    prep_frags_kernel<<<576, 256, 0, s2>>>(pe1_w2, theta_w, phi_w, g_w, W_w);
    linear_tc_kernel<<<dim3(NPTS / 64, 3), 256, LIN_SMEM, s2>>>(
        feats, 0, theta_b, phi_b, g_b, p_theta, p_phi, p_g, nullptr);

    // branch A (main stream): fused grid build + KNN
    build_grid_kernel<<<1, 1024>>>(coords);
    knn_grid_kernel<<<NPTS / 8, 256>>>(coords);

    // join
    cudaEventRecord(eJoin, s2);
    cudaStreamWaitEvent(0, eJoin, 0);

    attn_tc_kernel<<<NPTS / 8, 256, ATTN_SMEM_B>>>(coords, pe1_w1, pe1_b1, pe1_b2);

    // final: out = y @ W_w + W_b + feats (fp16 single-pass)
    linear_tc_kernel<<<dim3(NPTS / 64, 1), 256, LIN_SMEM>>>(
        p_y, 3, W_b, W_b, W_b, out, out, out, feats);

    cudaEventDestroy(eFork);
    cudaEventDestroy(eJoin);
    cudaStreamDestroy(s2);
}

// round 17
// speedup vs baseline: 1.0271x; 1.0271x over previous
#include <cuda_runtime.h>
#include <cuda_bf16.h>
#include <math_constants.h>
#include <cstdint>

#define NPTS 8192
#define CCH  256
#define KNB  16

typedef unsigned long long ull;

// ---------------- pack helpers ----------------
// f16x2: bits[15:0] = lo arg, bits[31:16] = hi arg
__device__ __forceinline__ uint32_t f16pack(float lo, float hi) {
    uint32_t r;
    asm("cvt.rn.f16x2.f32 %0, %1, %2;" : "=r"(r) : "f"(hi), "f"(lo));
    return r;
}

// mma.sync f16 m16n8k16 (baseline sm_80 PTX)
__device__ __forceinline__ void mma_f16(float* d,
                                        uint32_t a0, uint32_t a1, uint32_t a2, uint32_t a3,
                                        uint32_t b0, uint32_t b1) {
    asm volatile(
        "mma.sync.aligned.m16n8k16.row.col.f32.f16.f16.f32 "
        "{%0,%1,%2,%3}, {%4,%5,%6,%7}, {%8,%9}, {%0,%1,%2,%3};"
        : "+f"(d[0]), "+f"(d[1]), "+f"(d[2]), "+f"(d[3])
        : "r"(a0), "r"(a1), "r"(a2), "r"(a3), "r"(b0), "r"(b1));
}

// ---------------- scratch (device globals; no allocation APIs) ----------------
__device__ int    g_idx[NPTS * KNB];
__device__ float  g_theta[NPTS * CCH];
__device__ float  g_phi[NPTS * CCH];
__device__ float  g_gv[NPTS * CCH];
__device__ float  g_y[NPTS * CCH];
__device__ uint32_t g_w2f[32768];        // attn w2 -> fp16 B fragments
__device__ uint32_t g_wf[4 * 32768];     // theta/phi/g/W -> fp16 B fragments
// grid-KNN scratch
__device__ float4 g_spts[NPTS];
__device__ int    g_sid[NPTS];
__device__ int    g_cellcnt[512];
__device__ int    g_cellstart[513];

#define GRID_DIM 8
#define CELL_H   12.5f
#define INV_H    0.08f

__device__ __forceinline__ int cell_coord(float v) {
    int c = (int)(v * INV_H);
    return min(GRID_DIM - 1, max(0, c));
}

// ---------------- grid build ----------------
__global__ void hist_kernel(const float* __restrict__ coords) {
    int i = blockIdx.x * blockDim.x + threadIdx.x;
    if (i < NPTS) {
        int cx = cell_coord(coords[3 * i + 0]);
        int cy = cell_coord(coords[3 * i + 1]);
        int cz = cell_coord(coords[3 * i + 2]);
        atomicAdd(&g_cellcnt[(cz * GRID_DIM + cy) * GRID_DIM + cx], 1);
    }
}

__global__ void scan_kernel() {   // 1 block, 512 threads
    __shared__ int tmp[512];
    int t = threadIdx.x;
    tmp[t] = g_cellcnt[t];
    __syncthreads();
    for (int off = 1; off < 512; off <<= 1) {
        int a = (t >= off) ? tmp[t - off] : 0;
        __syncthreads();
        tmp[t] += a;
        __syncthreads();
    }
    g_cellstart[t + 1] = tmp[t];
    if (t == 0) g_cellstart[0] = 0;
    g_cellcnt[t] = 0;
}

__global__ void scatter_kernel(const float* __restrict__ coords) {
    int i = blockIdx.x * blockDim.x + threadIdx.x;
    if (i < NPTS) {
        float x = coords[3 * i + 0];
        float y = coords[3 * i + 1];
        float z = coords[3 * i + 2];
        int cell = (cell_coord(z) * GRID_DIM + cell_coord(y)) * GRID_DIM + cell_coord(x);
        int pos = g_cellstart[cell] + atomicAdd(&g_cellcnt[cell], 1);
        g_spts[pos] = make_float4(x, y, z, x * x + y * y + z * z);
        g_sid[pos] = i;
    }
}

// ---------------- grid KNN: warp/query, bitonic seed + lean exact inserts ----------------
__global__ __launch_bounds__(256) void knn_grid_kernel(const float* __restrict__ coords) {
    int warp = threadIdx.x >> 5;
    int lane = threadIdx.x & 31;
    int q = blockIdx.x * 8 + warp;

    float qx = coords[3 * q + 0];
    float qy = coords[3 * q + 1];
    float qz = coords[3 * q + 2];
    float qw = qx * qx + qy * qy + qz * qz;
    int cx = cell_coord(qx), cy = cell_coord(qy), cz = cell_coord(qz);

    ull slot = ~0ull;
    ull thr  = ~0ull;
    float thrf = CUDART_INF_F;
    bool seeded = false;

    auto scan_range = [&](int c0, int c1) {
        int st = g_cellstart[c0];
        int en = g_cellstart[c1 + 1];
        for (int jj = st; jj < en; jj += 32) {
            int id = jj + lane;
            ull key = ~0ull;
            if (id < en) {
                float4 p = g_spts[id];
                float dot = qx * p.x + qy * p.y + qz * p.z;
                float d2 = (qw + p.w) - 2.0f * dot;   // reference formula
                if (d2 <= thrf) {
                    unsigned u = __float_as_uint(d2);
                    u = ((int)u < 0) ? ~u : (u | 0x80000000u);
                    key = ((ull)u << 32) | (unsigned)g_sid[id];
                }
            }
            if (!seeded) {
#pragma unroll
                for (int k = 2; k <= 32; k <<= 1) {
#pragma unroll
                    for (int j = k >> 1; j > 0; j >>= 1) {
                        ull other = __shfl_xor_sync(0xffffffffu, key, j);
                        bool keepSmall = (((lane & k) == 0) == ((lane & j) == 0));
                        bool less = key < other;
                        key = (keepSmall == less) ? key : other;
                    }
                }
                slot = key;
                thr  = __shfl_sync(0xffffffffu, slot, 15);
                seeded = true;
            } else {
                unsigned mask = __ballot_sync(0xffffffffu, key < thr);
                if (mask) {
                    while (mask) {
                        int src = __ffs(mask) - 1;
                        mask &= mask - 1;
                        ull cand = __shfl_sync(0xffffffffu, key, src);
                        unsigned lt = __ballot_sync(0xffffffffu, (lane < 16) && (slot < cand));
                        int pos = __popc(lt);
                        ull prev = __shfl_up_sync(0xffffffffu, slot, 1);
                        if (lane >= pos && lane < 16) slot = (lane == pos) ? cand : prev;
                    }
                    thr = __shfl_sync(0xffffffffu, slot, 15);
                }
            }
        }
        unsigned hb = (unsigned)(thr >> 32);
        thrf = (hb == 0xffffffffu) ? CUDART_INF_F
             : ((hb & 0x80000000u) ? __uint_as_float(hb & 0x7fffffffu)
                                   : __uint_as_float(~hb));
    };

    int px0 = 1, px1 = 0, py0 = 1, py1 = 0, pz0 = 1, pz1 = 0;

    for (int s = 1; s <= GRID_DIM; ++s) {
        int x0 = max(cx - s, 0), x1 = min(cx + s, GRID_DIM - 1);
        int y0 = max(cy - s, 0), y1 = min(cy + s, GRID_DIM - 1);
        int z0 = max(cz - s, 0), z1 = min(cz + s, GRID_DIM - 1);

        for (int zz = z0; zz <= z1; ++zz)
        for (int yy = y0; yy <= y1; ++yy) {
            int rbase = (zz * GRID_DIM + yy) * GRID_DIM;
            bool inPrevZY = (zz >= pz0 && zz <= pz1 && yy >= py0 && yy <= py1);
            if (!inPrevZY) {
                scan_range(rbase + x0, rbase + x1);
            } else {
                if (x0 < px0) scan_range(rbase + x0, rbase + px0 - 1);
                if (px1 < x1) scan_range(rbase + px1 + 1, rbase + x1);
            }
        }

        bool covered = (x0 == 0 && x1 == GRID_DIM - 1 &&
                        y0 == 0 && y1 == GRID_DIM - 1 &&
                        z0 == 0 && z1 == GRID_DIM - 1);
        float fxl = (x0 > 0) ? qx - x0 * CELL_H : CUDART_INF_F;
        float fxh = (x1 < GRID_DIM - 1) ? (x1 + 1) * CELL_H - qx : CUDART_INF_F;
        float fyl = (y0 > 0) ? qy - y0 * CELL_H : CUDART_INF_F;
        float fyh = (y1 < GRID_DIM - 1) ? (y1 + 1) * CELL_H - qy : CUDART_INF_F;
        float fzl = (z0 > 0) ? qz - z0 * CELL_H : CUDART_INF_F;
        float fzh = (z1 < GRID_DIM - 1) ? (z1 + 1) * CELL_H - qz : CUDART_INF_F;
        float md = fminf(fminf(fminf(fxl, fxh), fminf(fyl, fyh)), fminf(fzl, fzh));
        if (covered || md * md > thrf + 0.5f) break;

        px0 = x0; px1 = x1; py0 = y0; py1 = y1; pz0 = z0; pz1 = z1;
    }

    if (lane < 16) g_idx[q * KNB + lane] = (int)(unsigned)(slot & 0xffffffffu);
}

// ---------------- prep: all weight fragments (fp16) in one launch ----------------
__global__ void prep_frags_kernel(const float* __restrict__ w2attn,
                                  const float* __restrict__ w0, const float* __restrict__ w1,
                                  const float* __restrict__ w2, const float* __restrict__ w3) {
    if (blockIdx.x < 128) {
        int tid = blockIdx.x * 256 + threadIdx.x;       // 0..32767
        int reg = tid & 1;
        int ln  = (tid >> 1) & 31;
        int nt  = (tid >> 6) & 7;
        int kt  = (tid >> 9) & 15;
        int cc  = (tid >> 13) & 3;
        int n = cc * 64 + nt * 8 + (ln >> 2);
        int k = kt * 16 + 2 * (ln & 3) + reg * 8;
        g_w2f[tid] = f16pack(w2attn[k * CCH + n], w2attn[(k + 1) * CCH + n]);
    } else {
        int tid = (blockIdx.x - 128) * 256 + threadIdx.x;  // 0..131071
        int m = tid >> 15;
        int r = tid & 32767;
        int reg = r & 1;
        int ln  = (r >> 1) & 31;
        int nt  = (r >> 6) & 31;
        int kt  = (r >> 11) & 15;
        int n = nt * 8 + (ln >> 2);
        int k = kt * 16 + 2 * (ln & 3) + reg * 8;
        const float* W = (m == 0) ? w0 : (m == 1) ? w1 : (m == 2) ? w2 : w3;
        g_wf[tid] = f16pack(W[k * CCH + n], W[(k + 1) * CCH + n]);
    }
}

// ---------------- tensor-core linear: fp16 single-pass ----------------
#define LIN_SMEM (64 * 132 * 4)

__global__ void __launch_bounds__(256, 2) linear_tc_kernel(
    const float* __restrict__ A, int m0,
    const float* __restrict__ b0_, const float* __restrict__ b1_, const float* __restrict__ b2_,
    float* __restrict__ o0, float* __restrict__ o1, float* __restrict__ o2,
    const float* __restrict__ resid)
{
    extern __shared__ uint32_t dsm[];
    uint32_t* sA = dsm;

    int mat = m0 + blockIdx.y;
    const float* bias = (blockIdx.y == 0) ? b0_ : (blockIdx.y == 1) ? b1_ : b2_;
    float*       out  = (blockIdx.y == 0) ? o0 : (blockIdx.y == 1) ? o1 : o2;

    int t = threadIdx.x;
    int lane = t & 31;
    int w = t >> 5;
    int wm = w & 3;
    int wn = w >> 2;
    int g = lane >> 2;
    int c4 = lane & 3;
    int row0 = blockIdx.x * 64;

    for (int idx = t; idx < 4096; idx += 256) {
        int row = idx >> 6;
        int qq = idx & 63;
        float4 v = *(const float4*)&A[(row0 + row) * CCH + qq * 4];
        *(uint2*)&sA[row * 132 + qq * 2] = make_uint2(f16pack(v.x, v.y), f16pack(v.z, v.w));
    }
    __syncthreads();

    float acc[16][4];
#pragma unroll
    for (int nt = 0; nt < 16; ++nt)
#pragma unroll
        for (int r = 0; r < 4; ++r) acc[nt][r] = 0.0f;

    int rA = wm * 16 + g;
    const uint32_t* bfrag = g_wf + mat * 32768;

#pragma unroll 2
    for (int kt = 0; kt < 16; ++kt) {
        uint32_t a0 = sA[rA * 132 + kt * 8 + c4];
        uint32_t a1 = sA[(rA + 8) * 132 + kt * 8 + c4];
        uint32_t a2 = sA[rA * 132 + kt * 8 + c4 + 4];
        uint32_t a3 = sA[(rA + 8) * 132 + kt * 8 + c4 + 4];
#pragma unroll
        for (int nt = 0; nt < 16; ++nt) {
            int ntg = wn * 16 + nt;
            uint2 bh = *(const uint2*)&bfrag[kt * 2048 + ntg * 64 + lane * 2];
            mma_f16(acc[nt], a0, a1, a2, a3, bh.x, bh.y);
        }
    }

#pragma unroll
    for (int nt = 0; nt < 16; ++nt) {
        int ntg = wn * 16 + nt;
        int n0 = ntg * 8 + 2 * c4;
        float2 bv = *(const float2*)&bias[n0];
        int r0 = row0 + rA;
        int r1 = r0 + 8;
        float2 v0 = make_float2(acc[nt][0] + bv.x, acc[nt][1] + bv.y);
        float2 v1 = make_float2(acc[nt][2] + bv.x, acc[nt][3] + bv.y);
        if (resid != nullptr) {
            float2 f0 = *(const float2*)&resid[r0 * CCH + n0];
            float2 f1 = *(const float2*)&resid[r1 * CCH + n0];
            v0.x += f0.x; v0.y += f0.y;
            v1.x += f1.x; v1.y += f1.y;
        }
        *(float2*)&out[r0 * CCH + n0] = v0;
        *(float2*)&out[r1 * CCH + n0] = v1;
    }
}

// ---------------- h-pair: 2 hidden values -> packed fp16 fragment reg ----------------
__device__ __forceinline__ uint32_t hpair16(float4 pa, float4 pb,
                                            float dx, float dy, float dz) {
    float h0 = fmaxf(fmaf(dz, pb.x, fmaf(dy, pa.z, fmaf(dx, pa.x, pb.z))), 0.0f);
    float h1 = fmaxf(fmaf(dz, pb.y, fmaf(dy, pa.w, fmaf(dx, pa.y, pb.w))), 0.0f);
    return f16pack(h0, h1);
}

// ---------------- attention: fp16 mma pe-GEMM, A-frags cached in smem ----------------
// smem (u32): HF[16384] (uint4[4096], thread-private A-frag cache, conflict-free)
//             | BH[8192] | W1P[1024] | DL[384] | ID[128]
#define ATTN_SMEM_U32 26112
#define ATTN_SMEM_B   (ATTN_SMEM_U32 * 4)

__global__ void __launch_bounds__(256) attn_tc_kernel(
    const float* __restrict__ coords,
    const float* __restrict__ pe1_w1, const float* __restrict__ pe1_b1,
    const float* __restrict__ pe1_b2)
{
    extern __shared__ uint32_t dsm[];
    uint4*    HF  = (uint4*)dsm;             // 4096 uint4 (64KB)
    uint32_t* BH  = dsm + 16384;             // 8192 u32 (32KB)
    float*    W1P = (float*)(dsm + 24576);   // 1024
    float*    DL  = (float*)(dsm + 25600);   // 384
    int*      ID  = (int*)(dsm + 25984);     // 128

    int t = threadIdx.x;
    int lane = t & 31;
    int w = t >> 5;
    int g = lane >> 2;
    int c4 = lane & 3;

    {
        int f = 4 * t;
#pragma unroll
        for (int u = 0; u < 4; ++u) {
            int ff = f + u, p = ff >> 3, comp = ff & 7;
            float v;
            if (comp < 6) v = pe1_w1[(comp >> 1) * CCH + 2 * p + (comp & 1)];
            else          v = pe1_b1[2 * p + (comp & 1)];
            W1P[ff] = v;
        }
    }
    if (t < 128) ID[t] = g_idx[blockIdx.x * 128 + t];
    __syncthreads();
    if (t < 128) {
        int nid = ID[t];
        int ip = blockIdx.x * 8 + (t >> 4);
#pragma unroll
        for (int d = 0; d < 3; ++d)
            DL[t * 3 + d] = coords[nid * 3 + d] - coords[ip * 3 + d];
    }
    __syncthreads();

    int rA = w * 16 + g, rB = rA + 8;
    float dxa = DL[rA * 3], dya = DL[rA * 3 + 1], dza = DL[rA * 3 + 2];
    float dxb = DL[rB * 3], dyb = DL[rB * 3 + 1], dzb = DL[rB * 3 + 2];
    int nid0 = ID[rA], nid1 = ID[rB];
    int ipt = blockIdx.x * 8 + w;

    const float4* w1p4 = (const float4*)W1P;

    // compute ALL fp16 A-fragments ONCE; park in thread-private smem slab.
    // identical arithmetic to the per-chunk recompute -> bit-identical pe.
#pragma unroll
    for (int kt = 0; kt < 16; ++kt) {
        int jp0 = kt * 8 + c4;
        float4 p0a = w1p4[jp0 * 2],     p0b = w1p4[jp0 * 2 + 1];
        float4 p1a = w1p4[jp0 * 2 + 8], p1b = w1p4[jp0 * 2 + 9];
        uint4 v;
        v.x = hpair16(p0a, p0b, dxa, dya, dza);
        v.y = hpair16(p0a, p0b, dxb, dyb, dzb);
        v.z = hpair16(p1a, p1b, dxa, dya, dza);
        v.w = hpair16(p1a, p1b, dxb, dyb, dzb);
        HF[kt * 256 + t] = v;     // stride 16B/thread -> conflict-free; private
    }

    for (int cc = 0; cc < 4; ++cc) {
        __syncthreads();
        {   // stage this n-chunk's fp16 B fragments (32KB)
            const uint4* sh = (const uint4*)(g_w2f + cc * 8192);
            uint4* dh = (uint4*)BH;
            for (int u = t; u < 2048; u += 256) dh[u] = sh[u];
        }
        __syncthreads();

        float acc[8][4];
#pragma unroll
        for (int nt = 0; nt < 8; ++nt)
#pragma unroll
            for (int r = 0; r < 4; ++r) acc[nt][r] = 0.0f;

#pragma unroll 4
        for (int kt = 0; kt < 16; ++kt) {
            uint4 av = HF[kt * 256 + t];     // 1 LDS.128 replaces 4 hpair recomputes
            int bbase = kt * 512 + lane * 2;
#pragma unroll
            for (int nt = 0; nt < 8; ++nt) {
                uint2 bh = *(const uint2*)&BH[bbase + nt * 64];
                mma_f16(acc[nt], av.x, av.y, av.z, av.w, bh.x, bh.y);
            }
        }

#pragma unroll
        for (int nt = 0; nt < 8; ++nt) {
            int n0 = cc * 64 + nt * 8 + 2 * c4;
            float2 b2v = *(const float2*)&pe1_b2[n0];
            float2 th  = *(const float2*)&g_theta[ipt * CCH + n0];
            float2 ph0 = *(const float2*)&g_phi[nid0 * CCH + n0];
            float2 ph1 = *(const float2*)&g_phi[nid1 * CCH + n0];

            float pe00 = acc[nt][0] + b2v.x, pe01 = acc[nt][1] + b2v.y;
            float pe10 = acc[nt][2] + b2v.x, pe11 = acc[nt][3] + b2v.y;

            float v00 = (pe00 * (th.x - ph0.x) + pe00) * 0.0625f;
            float v01 = (pe01 * (th.y - ph0.y) + pe01) * 0.0625f;
            float v10 = (pe10 * (th.x - ph1.x) + pe10) * 0.0625f;
            float v11 = (pe11 * (th.y - ph1.y) + pe11) * 0.0625f;

            float m0 = fmaxf(v00, v10), m1 = fmaxf(v01, v11);
#pragma unroll
            for (int off = 4; off <= 16; off <<= 1) {
                m0 = fmaxf(m0, __shfl_xor_sync(0xffffffffu, m0, off));
                m1 = fmaxf(m1, __shfl_xor_sync(0xffffffffu, m1, off));
            }
            float e00 = expf(v00 - m0), e10 = expf(v10 - m0);
            float e01 = expf(v01 - m1), e11 = expf(v11 - m1);
            float s0 = e00 + e10, s1 = e01 + e11;
#pragma unroll
            for (int off = 4; off <= 16; off <<= 1) {
                s0 += __shfl_xor_sync(0xffffffffu, s0, off);
                s1 += __shfl_xor_sync(0xffffffffu, s1, off);
            }
            float2 gv0 = *(const float2*)&g_gv[nid0 * CCH + n0];
            float2 gv1 = *(const float2*)&g_gv[nid1 * CCH + n0];
            float y0 = e00 * gv0.x + e10 * gv1.x;
            float y1 = e01 * gv0.y + e11 * gv1.y;
#pragma unroll
            for (int off = 4; off <= 16; off <<= 1) {
                y0 += __shfl_xor_sync(0xffffffffu, y0, off);
                y1 += __shfl_xor_sync(0xffffffffu, y1, off);
            }
            if (g == 0)
                *(float2*)&g_y[ipt * CCH + n0] = make_float2(y0 / s0, y1 / s1);
        }
    }
}

// ---------------- launch: fork KNN chain and GEMM-prep chain onto parallel streams ----------------
extern "C" void kernel_launch(void* const* d_in, const int* in_sizes, int n_in,
                              void* d_out, int out_size) {
    const float* coords  = (const float*)d_in[0];
    const float* feats   = (const float*)d_in[1];
    const float* theta_w = (const float*)d_in[2];
    const float* theta_b = (const float*)d_in[3];
    const float* phi_w   = (const float*)d_in[4];
    const float* phi_b   = (const float*)d_in[5];
    const float* g_w     = (const float*)d_in[6];
    const float* g_b     = (const float*)d_in[7];
    const float* pe1_w1  = (const float*)d_in[8];
    const float* pe1_b1  = (const float*)d_in[9];
    const float* pe1_w2  = (const float*)d_in[10];
    const float* pe1_b2  = (const float*)d_in[11];
    const float* W_w     = (const float*)d_in[12];
    const float* W_b     = (const float*)d_in[13];
    float* out = (float*)d_out;

    float *p_theta, *p_phi, *p_g, *p_y;
    void* p_cnt;
    cudaGetSymbolAddress((void**)&p_theta, g_theta);
    cudaGetSymbolAddress((void**)&p_phi,   g_phi);
    cudaGetSymbolAddress((void**)&p_g,     g_gv);
    cudaGetSymbolAddress((void**)&p_y,     g_y);
    cudaGetSymbolAddress(&p_cnt,           g_cellcnt);

    cudaFuncSetAttribute(attn_tc_kernel,
                         cudaFuncAttributeMaxDynamicSharedMemorySize, ATTN_SMEM_B);
    cudaFuncSetAttribute(linear_tc_kernel,
                         cudaFuncAttributeMaxDynamicSharedMemorySize, LIN_SMEM);

    cudaStream_t s2;
    cudaStreamCreateWithFlags(&s2, cudaStreamNonBlocking);
    cudaEvent_t eFork, eJoin;
    cudaEventCreateWithFlags(&eFork, cudaEventDisableTiming);
    cudaEventCreateWithFlags(&eJoin, cudaEventDisableTiming);

    cudaEventRecord(eFork, 0);
    cudaStreamWaitEvent(s2, eFork, 0);

    // branch B (s2): weight fragments + theta/phi/g linears
    prep_frags_kernel<<<640, 256, 0, s2>>>(pe1_w2, theta_w, phi_w, g_w, W_w);
    linear_tc_kernel<<<dim3(NPTS / 64, 3), 256, LIN_SMEM, s2>>>(
        feats, 0, theta_b, phi_b, g_b, p_theta, p_phi, p_g, nullptr);

    // branch A (main stream): grid build + KNN
    cudaMemsetAsync(p_cnt, 0, 512 * sizeof(int), 0);
    hist_kernel<<<NPTS / 256, 256>>>(coords);
    scan_kernel<<<1, 512>>>();
    scatter_kernel<<<NPTS / 256, 256>>>(coords);
    knn_grid_kernel<<<NPTS / 8, 256>>>(coords);

    // join
    cudaEventRecord(eJoin, s2);
    cudaStreamWaitEvent(0, eJoin, 0);

    attn_tc_kernel<<<NPTS / 8, 256, ATTN_SMEM_B>>>(coords, pe1_w1, pe1_b1, pe1_b2);

    // final: out = y @ W_w + W_b + feats (fp16 single-pass)
    linear_tc_kernel<<<dim3(NPTS / 64, 1), 256, LIN_SMEM>>>(
        p_y, 3, W_b, W_b, W_b, out, out, out, feats);

    cudaEventDestroy(eFork);
    cudaEventDestroy(eJoin);
    cudaStreamDestroy(s2);
}